// round 8
// baseline (speedup 1.0000x reference)
#include <cuda_runtime.h>
#include <cuda_bf16.h>
#include <cstdint>

#define BB 256   // batch
#define TT 512   // encoder steps
#define FF 64    // input features
#define HH 1024  // hidden
#define TLEN 64  // decoder steps
#define N3 3072  // 3*H output columns (gate-interleaved)
#define NCT 48   // tensor chunks (aug K 3072 / 64)
#define NCF 16   // ffma chunks (K 1024 / 64)
#define NSTG_T 8 // tensor ring stages (power of 2, proven parity math)
#define NSTG_F 3 // ffma ring stages

#define AT_B 8192                 // tensor A tile: 64 rows x 128B (SW128)
#define BT_B 6144                 // tensor B tile: 48 rows x 128B
#define STG_T (AT_B + BT_B)       // 14336
#define AF_B 16384                // ffma A^T tile: [64k][64m] f32
#define BF_B 12288                // ffma B^T tile: [64k][48n] f32
#define STG_F (AF_B + BF_B)       // 28672
#define HDR 1024
#define OFF_T HDR                 // 1024
#define OFF_F (HDR + NSTG_T * STG_T)          // 115712
#define SMEMSZ (OFF_F + NSTG_F * STG_F)       // 201728

__device__ __forceinline__ uint32_t sw128(uint32_t off) { return off ^ ((off >> 3) & 0x70); }

// ---------------- device scratch ----------------
__device__ __align__(128) __nv_bfloat16 g_Wt[2][32][NCT][48 * 64];   // 18.9 MB
__device__ __align__(128) float g_Wf[2][32][NCF][64][48];            // 12.6 MB
__device__ __align__(128) __nv_bfloat16 g_ht[2][4][NCT][64 * 64];    // 3 MB
__device__ __align__(128) float g_hf[2][4][NCF][64][64];             // 4 MB
__device__ float g_bih_e[N3], g_bhh_e[N3], g_bih_d[N3], g_bhh_d[N3];
__device__ float g_Wihp_e[(size_t)HH * 192];
__device__ float g_Wih_d[N3];

// ---------------- PTX helpers ----------------
__device__ __forceinline__ void cp16(uint32_t smaddr, const void* g) {
    asm volatile("cp.async.cg.shared.global [%0], [%1], 16;" :: "r"(smaddr), "l"(g));
}
__device__ __forceinline__ void ldsm_x4(uint32_t* r, uint32_t addr) {
    asm volatile("ldmatrix.sync.aligned.m8n8.x4.shared.b16 {%0,%1,%2,%3}, [%4];"
                 : "=r"(r[0]), "=r"(r[1]), "=r"(r[2]), "=r"(r[3]) : "r"(addr));
}
__device__ __forceinline__ void ldsm_x2(uint32_t* r, uint32_t addr) {
    asm volatile("ldmatrix.sync.aligned.m8n8.x2.shared.b16 {%0,%1}, [%2];"
                 : "=r"(r[0]), "=r"(r[1]) : "r"(addr));
}
__device__ __forceinline__ void mma_bf16(float* c, const uint32_t* a, uint32_t b0, uint32_t b1) {
    asm volatile("mma.sync.aligned.m16n8k16.row.col.f32.bf16.bf16.f32 "
                 "{%0,%1,%2,%3}, {%4,%5,%6,%7}, {%8,%9}, {%0,%1,%2,%3};"
                 : "+f"(c[0]), "+f"(c[1]), "+f"(c[2]), "+f"(c[3])
                 : "r"(a[0]), "r"(a[1]), "r"(a[2]), "r"(a[3]), "r"(b0), "r"(b1));
}
__device__ __forceinline__ void mbar_init(uint32_t mbar, uint32_t cnt) {
    asm volatile("mbarrier.init.shared.b64 [%0], %1;" :: "r"(mbar), "r"(cnt) : "memory");
}
__device__ __forceinline__ void mbar_arrive(uint32_t mbar) {
    asm volatile("mbarrier.arrive.shared.b64 _, [%0];" :: "r"(mbar) : "memory");
}
__device__ __forceinline__ void mbar_expect_tx(uint32_t mbar, uint32_t bytes) {
    asm volatile("mbarrier.arrive.expect_tx.shared.b64 _, [%0], %1;"
                 :: "r"(mbar), "r"(bytes) : "memory");
}
__device__ __forceinline__ void mbar_wait(uint32_t mbar, uint32_t parity) {
    asm volatile(
        "{\n\t.reg .pred P1;\n\t"
        "WL_%=:\n\t"
        "mbarrier.try_wait.parity.acquire.cta.shared::cta.b64 P1, [%0], %1, 0x989680;\n\t"
        "@P1 bra.uni WD_%=;\n\t"
        "bra.uni WL_%=;\n\t"
        "WD_%=:\n\t}"
        :: "r"(mbar), "r"(parity) : "memory");
}
__device__ __forceinline__ void bulk_g2s(uint32_t dst, const void* src, uint32_t bytes, uint32_t mbar) {
    asm volatile("cp.async.bulk.shared::cluster.global.mbarrier::complete_tx::bytes "
                 "[%0], [%1], %2, [%3];"
                 :: "r"(dst), "l"(src), "r"(bytes), "r"(mbar) : "memory");
}
__device__ __forceinline__ void ffma2(uint64_t& d, uint64_t a, uint64_t b) {
    asm volatile("fma.rn.f32x2 %0, %1, %2, %0;" : "+l"(d) : "l"(a), "l"(b));
}
__device__ __forceinline__ uint64_t pk(float x, float y) {
    uint64_t d; asm("mov.b64 %0, {%1,%2};" : "=l"(d) : "f"(x), "f"(y)); return d;
}
__device__ __forceinline__ void upk(uint64_t d, float& x, float& y) {
    asm("mov.b64 {%0,%1}, %2;" : "=f"(x), "=f"(y) : "l"(d));
}
__device__ __forceinline__ void lds_f4(float4& v, uint32_t a) {
    asm volatile("ld.shared.v4.f32 {%0,%1,%2,%3}, [%4];"
                 : "=f"(v.x), "=f"(v.y), "=f"(v.z), "=f"(v.w) : "r"(a));
}
__device__ __forceinline__ float lds_f(uint32_t a) {
    float v; asm volatile("ld.shared.f32 %0, [%1];" : "=f"(v) : "r"(a)); return v;
}

// ---------------- prep: tensor aug weights (cols 0..47 of each 96-tile) ----------------
__global__ void prep_wt(const float* __restrict__ encW, const float* __restrict__ decW) {
    size_t idx = (size_t)blockIdx.x * blockDim.x + threadIdx.x;
    const size_t one = (size_t)1536 * 3072;
    if (idx >= 2 * one) return;
    int which = idx >= one;
    size_t rem = which ? idx - one : idx;
    int jt = (int)(rem / 3072);
    int k  = (int)(rem % 3072);
    int nb = jt / 48, jr = jt % 48;
    int u = nb * 32 + jr / 3, g = jr % 3;
    const float* W = which ? decW : encW;
    float w = W[(size_t)(g * HH + u) * HH + (k & 1023)];
    __nv_bfloat16 hi = __float2bfloat16(w);
    __nv_bfloat16 out = (k < 2048) ? hi : __float2bfloat16(w - __bfloat162float(hi));
    uint32_t swb = sw128((uint32_t)(jr * 128 + (k & 63) * 2));
    g_Wt[which][nb][k >> 6][swb >> 1] = out;
}

// ---------------- prep: ffma fp32 transposed weights (cols 48..95 of each tile) ----------------
__global__ void prep_wf(const float* __restrict__ encW, const float* __restrict__ decW) {
    size_t idx = (size_t)blockIdx.x * blockDim.x + threadIdx.x;
    const size_t one = (size_t)1536 * 1024;
    if (idx >= 2 * one) return;
    int which = idx >= one;
    size_t rem = which ? idx - one : idx;
    int jf = (int)(rem / 1024);
    int k  = (int)(rem % 1024);
    int nb = jf / 48, n = jf % 48;
    int u = nb * 32 + 16 + n / 3, g = n % 3;
    const float* W = which ? decW : encW;
    g_Wf[which][nb][k >> 6][k & 63][n] = W[(size_t)(g * HH + u) * HH + k];
}

// ---------------- prep: biases, W_ih, zero h, init d_out ----------------
__global__ void prep_misc(const float* __restrict__ ebih, const float* __restrict__ ebhh,
                          const float* __restrict__ dbih, const float* __restrict__ dbhh,
                          const float* __restrict__ eWih, const float* __restrict__ dWih,
                          const float* __restrict__ fcb, float* __restrict__ dout) {
    int tid = blockIdx.x * blockDim.x + threadIdx.x;
    int stride = gridDim.x * blockDim.x;
    for (int i = tid; i < N3; i += stride) {
        int u = i / 3, g = i - 3 * u;
        int o = g * HH + u;
        g_bih_e[i] = ebih[o];
        g_bhh_e[i] = ebhh[o];
        g_bih_d[i] = dbih[o];
        g_bhh_d[i] = dbhh[o];
        g_Wih_d[i] = dWih[o];
    }
    for (int i = tid; i < HH * 192; i += stride) {
        int u = i / 192, rem = i - u * 192;
        int g = rem >> 6, f = rem & 63;
        g_Wihp_e[i] = eWih[(size_t)(g * HH + u) * FF + f];
    }
    const int nt = 2 * 4 * NCT * 4096 / 2;
    for (int i = tid; i < nt; i += stride) ((uint32_t*)g_ht)[i] = 0u;
    const int nf = 2 * 4 * NCF * 4096;
    for (int i = tid; i < nf; i += stride) ((float*)g_hf)[i] = 0.f;
    for (int i = tid; i < BB * TLEN; i += stride) dout[i] = fcb[0];
}

// ---------------- step kernel: 4 tensor warps + 4 ffma warps ----------------
// grid (32, 4): nb = 96-col tile (48 tensor + 48 ffma), mb = 64-row batch tile.
__global__ __launch_bounds__(256) void gru_step_kernel(
    int t, int mode, int par,
    const float* __restrict__ x, const float* __restrict__ fcW, float* __restrict__ dout)
{
    const float* __restrict__ bih = mode ? g_bih_d : g_bih_e;
    const float* __restrict__ bhh = mode ? g_bhh_d : g_bhh_e;

    extern __shared__ __align__(16) unsigned char smem_raw[];
    const int tid = threadIdx.x;
    const int lane = tid & 31, warp = tid >> 5;
    const int nb = blockIdx.x, mb = blockIdx.y;

    const uint32_t smB = (uint32_t)__cvta_generic_to_shared(smem_raw);
    const uint32_t fullT = smB, emptyT = smB + 64;

    const __nv_bfloat16* __restrict__ At = &g_ht[par][mb][0][0];
    const __nv_bfloat16* __restrict__ Bt = &g_Wt[mode][nb][0][0];
    const float* __restrict__ Af = &g_hf[par][mb][0][0][0];
    const float* __restrict__ Bf = &g_Wf[mode][nb][0][0][0];

    if (tid == 0) {
        #pragma unroll
        for (int s = 0; s < NSTG_T; s++) { mbar_init(fullT + 8 * s, 1); mbar_init(emptyT + 8 * s, 4); }
    }
    __syncthreads();

    float* Csm = (float*)(smem_raw + HDR);               // 64 x 96, pitch 99 (post-loop)
    float* Xs  = (float*)(smem_raw + HDR + 25600);

    if (warp < 4) {
        // ================= tensor warps: cols 0..47, aug K=3072 (R6-proven ring) =================
        auto issue_t = [&](int c) {
            const int s = c & (NSTG_T - 1);
            const uint32_t m_ = fullT + 8 * s;
            mbar_expect_tx(m_, STG_T);
            const uint32_t d = smB + OFF_T + s * STG_T;
            bulk_g2s(d,        At + (size_t)c * 4096, AT_B, m_);
            bulk_g2s(d + AT_B, Bt + (size_t)c * 3072, BT_B, m_);
        };
        if (tid == 0) {
            #pragma unroll
            for (int s = 0; s < NSTG_T - 1; s++) issue_t(s);
        }

        const int wm = warp >> 1, wn = warp & 1;         // 2x2 warps, 32x24 tiles
        float acc[2][3][4];
        #pragma unroll
        for (int mi = 0; mi < 2; mi++)
            #pragma unroll
            for (int ni = 0; ni < 3; ni++)
                #pragma unroll
                for (int q = 0; q < 4; q++) acc[mi][ni][q] = 0.f;

        for (int c = 0; c < NCT; c++) {
            if (tid == 0) {
                int cn = c + NSTG_T - 1;
                if (cn < NCT) {
                    int r = cn >> 3;
                    if (r >= 1) mbar_wait(emptyT + 8 * (cn & (NSTG_T - 1)), (r - 1) & 1);
                    issue_t(cn);
                }
            }
            mbar_wait(fullT + 8 * (c & (NSTG_T - 1)), (c >> 3) & 1);
            const uint32_t sA = smB + OFF_T + (c & (NSTG_T - 1)) * STG_T;
            const uint32_t sB2 = sA + AT_B;
            #pragma unroll
            for (int ks = 0; ks < 4; ks++) {
                uint32_t ra[2][4], rb[3][2];
                #pragma unroll
                for (int mi = 0; mi < 2; mi++) {
                    uint32_t off = (uint32_t)((wm * 32 + mi * 16 + (lane & 15)) * 128
                                              + ks * 32 + (lane >> 4) * 16);
                    ldsm_x4(ra[mi], sA + sw128(off));
                }
                #pragma unroll
                for (int ni = 0; ni < 3; ni++) {
                    uint32_t off = (uint32_t)((wn * 24 + ni * 8 + (lane & 7)) * 128
                                              + ks * 32 + ((lane >> 3) & 1) * 16);
                    ldsm_x2(rb[ni], sB2 + sw128(off));
                }
                #pragma unroll
                for (int mi = 0; mi < 2; mi++)
                    #pragma unroll
                    for (int ni = 0; ni < 3; ni++)
                        mma_bf16(acc[mi][ni], ra[mi], rb[ni][0], rb[ni][1]);
            }
            if (lane == 0) mbar_arrive(emptyT + 8 * (c & (NSTG_T - 1)));
        }
        __syncthreads();
        #pragma unroll
        for (int mi = 0; mi < 2; mi++)
            #pragma unroll
            for (int ni = 0; ni < 3; ni++) {
                int m = wm * 32 + mi * 16 + (lane >> 2);
                int n = wn * 24 + ni * 8 + ((lane & 3) << 1);
                Csm[m * 99 + n]           = acc[mi][ni][0];
                Csm[m * 99 + n + 1]       = acc[mi][ni][1];
                Csm[(m + 8) * 99 + n]     = acc[mi][ni][2];
                Csm[(m + 8) * 99 + n + 1] = acc[mi][ni][3];
            }
    } else {
        // ================= ffma warps: cols 48..95, exact fp32 K=1024 (cp.async ring) =======
        const int tf = tid - 128;                        // 0..127
        const int m0 = (tf >> 4) * 8;                    // 8 rows per thread
        const int n0 = (tf & 15) * 3;                    // 3 cols per thread

        // per-thread cp.async loads of chunk c into slot c%3
        auto issue_f = [&](int c) {
            const uint32_t d = smB + OFF_F + (c % NSTG_F) * STG_F;
            const float* srcA = Af + (size_t)c * 4096;
            const float* srcB = Bf + (size_t)c * 3072;
            #pragma unroll
            for (int q = 0; q < 8; q++) {               // A: 16384B = 128 thr x 8 x 16B
                int idx = tf + q * 128;
                cp16(d + idx * 16, srcA + idx * 4);
            }
            #pragma unroll
            for (int q = 0; q < 6; q++) {               // B: 12288B = 128 thr x 6 x 16B
                int idx = tf + q * 128;
                cp16(d + AF_B + idx * 16, srcB + idx * 4);
            }
        };

        issue_f(0); asm volatile("cp.async.commit_group;" ::: "memory");
        issue_f(1); asm volatile("cp.async.commit_group;" ::: "memory");

        uint64_t acc2[12];
        #pragma unroll
        for (int q = 0; q < 12; q++) acc2[q] = 0ull;

        for (int c = 0; c < NCF; c++) {
            asm volatile("cp.async.wait_group 1;" ::: "memory");
            asm volatile("bar.sync 1, 128;" ::: "memory");
            // slot (c+2)%3 == slot of c-1, free now that all ffma warps passed this barrier
            if (c + 2 < NCF) issue_f(c + 2);
            asm volatile("cp.async.commit_group;" ::: "memory");

            const uint32_t sA = smB + OFF_F + (c % NSTG_F) * STG_F;
            const uint32_t sB2 = sA + AF_B;
            #pragma unroll 4
            for (int k = 0; k < 64; k++) {
                float4 a0, a1;
                lds_f4(a0, sA + (uint32_t)(k * 256 + m0 * 4));
                lds_f4(a1, sA + (uint32_t)(k * 256 + m0 * 4 + 16));
                float b0 = lds_f(sB2 + (uint32_t)(k * 192 + n0 * 4));
                float b1 = lds_f(sB2 + (uint32_t)(k * 192 + n0 * 4 + 4));
                float b2 = lds_f(sB2 + (uint32_t)(k * 192 + n0 * 4 + 8));
                uint64_t A0 = pk(a0.x, a0.y), A1 = pk(a0.z, a0.w);
                uint64_t A2 = pk(a1.x, a1.y), A3 = pk(a1.z, a1.w);
                uint64_t B0 = pk(b0, b0), B1 = pk(b1, b1), B2 = pk(b2, b2);
                ffma2(acc2[0], A0, B0); ffma2(acc2[1], A1, B0);
                ffma2(acc2[2], A2, B0); ffma2(acc2[3], A3, B0);
                ffma2(acc2[4], A0, B1); ffma2(acc2[5], A1, B1);
                ffma2(acc2[6], A2, B1); ffma2(acc2[7], A3, B1);
                ffma2(acc2[8], A0, B2); ffma2(acc2[9], A1, B2);
                ffma2(acc2[10], A2, B2); ffma2(acc2[11], A3, B2);
            }
        }
        __syncthreads();
        #pragma unroll
        for (int j = 0; j < 3; j++)
            #pragma unroll
            for (int p = 0; p < 4; p++) {
                float lo, hi;
                upk(acc2[j * 4 + p], lo, hi);
                Csm[(m0 + 2 * p) * 99     + 48 + n0 + j] = lo;
                Csm[(m0 + 2 * p + 1) * 99 + 48 + n0 + j] = hi;
            }
    }

    if (mode == 0) {
        #pragma unroll
        for (int q = 0; q < 4; q++) {
            int id = tid + q * 256;
            int r = id >> 4, c4 = id & 15;
            ((float4*)Xs)[r * 16 + c4] =
                *(const float4*)(x + ((size_t)(mb * 64 + r) * TT + t) * FF + c4 * 4);
        }
    }
    __syncthreads();

    // ---- fused GRU epilogue: thread owns (row bl, 8 units) ----
    const int bl = tid >> 2, uq = tid & 3;
    const int b = mb * 64 + bl;
    float inp = 0.f;
    if (mode && t > 0) inp = dout[b * TLEN + (t - 1)];
    float fcsum = 0.f;
    const float4* xs4 = (const float4*)(Xs + bl * 64);
    __nv_bfloat16* __restrict__ htd = &g_ht[par ^ 1][mb][0][0];
    float* __restrict__ hfd = &g_hf[par ^ 1][mb][0][0][0];
    const float* __restrict__ hfs = &g_hf[par][mb][0][0][0];

    #pragma unroll
    for (int i = 0; i < 8; i++) {
        int ul = uq * 8 + i;
        int u = nb * 32 + ul;
        float ar = Csm[bl * 99 + ul * 3 + 0];
        float az = Csm[bl * 99 + ul * 3 + 1];
        float an = Csm[bl * 99 + ul * 3 + 2];
        float gr, gz, gn;
        if (mode == 0) {
            gr = gz = gn = 0.f;
            const float4* wr4 = (const float4*)(g_Wihp_e + (size_t)u * 192);
            #pragma unroll
            for (int q = 0; q < 16; q++) {
                float4 xv = xs4[q];
                float4 a = wr4[q], bq = wr4[16 + q], cq = wr4[32 + q];
                gr += xv.x * a.x + xv.y * a.y + xv.z * a.z + xv.w * a.w;
                gz += xv.x * bq.x + xv.y * bq.y + xv.z * bq.z + xv.w * bq.w;
                gn += xv.x * cq.x + xv.y * cq.y + xv.z * cq.z + xv.w * cq.w;
            }
        } else {
            gr = inp * g_Wih_d[u * 3 + 0];
            gz = inp * g_Wih_d[u * 3 + 1];
            gn = inp * g_Wih_d[u * 3 + 2];
        }
        float hprev = hfs[(size_t)(u >> 6) * 4096 + (u & 63) * 64 + bl];
        float rg = 1.f / (1.f + __expf(-(gr + bih[u * 3 + 0] + ar + bhh[u * 3 + 0])));
        float zg = 1.f / (1.f + __expf(-(gz + bih[u * 3 + 1] + az + bhh[u * 3 + 1])));
        float ng = tanhf(gn + bih[u * 3 + 2] + rg * (an + bhh[u * 3 + 2]));
        float hn = (1.f - zg) * ng + zg * hprev;
        __nv_bfloat16 hi = __float2bfloat16(hn);
        __nv_bfloat16 lo = __float2bfloat16(hn - __bfloat162float(hi));
        const uint32_t swo = sw128((uint32_t)(bl * 128 + (u & 63) * 2));
        *(__nv_bfloat16*)((char*)htd + (size_t)(u >> 6) * AT_B + swo)        = hi;
        *(__nv_bfloat16*)((char*)htd + (size_t)(32 + (u >> 6)) * AT_B + swo) = hi;
        *(__nv_bfloat16*)((char*)htd + (size_t)(16 + (u >> 6)) * AT_B + swo) = lo;
        hfd[(size_t)(u >> 6) * 4096 + (u & 63) * 64 + bl] = hn;
        if (mode) fcsum += hn * fcW[u];
    }
    if (mode) {
        fcsum += __shfl_down_sync(0xffffffffu, fcsum, 2, 4);
        fcsum += __shfl_down_sync(0xffffffffu, fcsum, 1, 4);
        if (uq == 0) atomicAdd(&dout[b * TLEN + t], fcsum);
    }
}

// ---------------- host launch ----------------
extern "C" void kernel_launch(void* const* d_in, const int* in_sizes, int n_in,
                              void* d_out, int out_size) {
    const float* x    = (const float*)d_in[0];
    const float* eWih = (const float*)d_in[1];
    const float* eWhh = (const float*)d_in[2];
    const float* ebih = (const float*)d_in[3];
    const float* ebhh = (const float*)d_in[4];
    const float* dWih = (const float*)d_in[5];
    const float* dWhh = (const float*)d_in[6];
    const float* dbih = (const float*)d_in[7];
    const float* dbhh = (const float*)d_in[8];
    const float* fcW  = (const float*)d_in[9];
    const float* fcb  = (const float*)d_in[10];
    float* out = (float*)d_out;

    cudaFuncSetAttribute(gru_step_kernel,
                         cudaFuncAttributeMaxDynamicSharedMemorySize, SMEMSZ);

    prep_wt<<<(unsigned)((2 * (size_t)1536 * 3072 + 255) / 256), 256>>>(eWhh, dWhh);
    prep_wf<<<(unsigned)((2 * (size_t)1536 * 1024 + 255) / 256), 256>>>(eWhh, dWhh);
    prep_misc<<<1024, 256>>>(ebih, ebhh, dbih, dbhh, eWih, dWih, fcb, out);

    dim3 grid(N3 / 96, BB / 64);   // (32, 4)
    for (int t = 0; t < TT; t++)
        gru_step_kernel<<<grid, 256, SMEMSZ>>>(t, 0, t & 1, x, fcW, out);
    for (int s = 0; s < TLEN; s++)
        gru_step_kernel<<<grid, 256, SMEMSZ>>>(s, 1, s & 1, x, fcW, out);
}